// round 1
// baseline (speedup 1.0000x reference)
#include <cuda_runtime.h>

// Problem constants
#define BSZ 64
#define NN_ 256
#define TT_ 512
#define NT_ (NN_*TT_)          // 131072
#define BNT (BSZ*NN_*TT_)      // 8388608
#define BNN (BSZ*NN_*NN_)      // 4194304
#define NMAX 51                // 256/5

// -------- scratch (device globals; no allocation allowed) --------
__device__ float g_xln[BNT];
__device__ float g_xbn[BNT];
__device__ float g_xp [BNT];
__device__ float g_sc [BNN];   // scores -> A -> L (in place)
__device__ float g_tx1[BNT];
__device__ float g_tx2[BNT];
__device__ float g_mu  [BSZ];
__device__ float g_rstd[BSZ];
__device__ float g_bns [NN_];
__device__ float g_bnh [NN_];
__device__ float g_dinv[BSZ*NN_];

// ======================= LayerNorm =======================
__global__ void ln_stats_kernel(const float* __restrict__ x) {
    int b = blockIdx.x;
    const float4* xb = (const float4*)(x + (long)b * NT_);
    float s = 0.f, q = 0.f;
    for (int i = threadIdx.x; i < NT_/4; i += 256) {
        float4 v = xb[i];
        s += v.x + v.y + v.z + v.w;
        q += v.x*v.x + v.y*v.y + v.z*v.z + v.w*v.w;
    }
    __shared__ float ss[256], sq[256];
    ss[threadIdx.x] = s; sq[threadIdx.x] = q;
    __syncthreads();
    for (int o = 128; o > 0; o >>= 1) {
        if (threadIdx.x < o) { ss[threadIdx.x] += ss[threadIdx.x+o]; sq[threadIdx.x] += sq[threadIdx.x+o]; }
        __syncthreads();
    }
    if (threadIdx.x == 0) {
        float mu  = ss[0] / (float)NT_;
        float var = sq[0] / (float)NT_ - mu * mu;
        g_mu[b] = mu;
        g_rstd[b] = rsqrtf(var + 1e-5f);
    }
}

__global__ void ln_apply_kernel(const float* __restrict__ x,
                                const float* __restrict__ lw,
                                const float* __restrict__ lb) {
    int i4 = blockIdx.x * 256 + threadIdx.x;      // over BNT/4
    int base = i4 * 4;
    int b  = base / NT_;
    int nt4 = (base % NT_) / 4;
    float mu = g_mu[b], rs = g_rstd[b];
    float4 v = ((const float4*)x)[i4];
    float4 w = ((const float4*)lw)[nt4];
    float4 bb = ((const float4*)lb)[nt4];
    float4 o;
    o.x = (v.x - mu) * rs * w.x + bb.x;
    o.y = (v.y - mu) * rs * w.y + bb.y;
    o.z = (v.z - mu) * rs * w.z + bb.z;
    o.w = (v.w - mu) * rs * w.w + bb.w;
    ((float4*)g_xln)[i4] = o;
}

// ======================= BatchNorm over (b,t) per node =======================
__global__ void bn_stats_kernel(const float* __restrict__ bg,
                                const float* __restrict__ bb) {
    int n = blockIdx.x;
    float s = 0.f, q = 0.f;
    for (int i = threadIdx.x; i < (BSZ*TT_)/4; i += 256) {
        int base = i * 4;
        int b = base / TT_;
        int t = base % TT_;
        float4 v = *(const float4*)&g_xln[((long)b * NN_ + n) * TT_ + t];
        s += v.x + v.y + v.z + v.w;
        q += v.x*v.x + v.y*v.y + v.z*v.z + v.w*v.w;
    }
    __shared__ float ss[256], sq[256];
    ss[threadIdx.x] = s; sq[threadIdx.x] = q;
    __syncthreads();
    for (int o = 128; o > 0; o >>= 1) {
        if (threadIdx.x < o) { ss[threadIdx.x] += ss[threadIdx.x+o]; sq[threadIdx.x] += sq[threadIdx.x+o]; }
        __syncthreads();
    }
    if (threadIdx.x == 0) {
        float cnt  = (float)(BSZ * TT_);
        float mean = ss[0] / cnt;
        float var  = sq[0] / cnt - mean * mean;
        float sc   = bg[n] * rsqrtf(var + 1e-5f);
        g_bns[n] = sc;
        g_bnh[n] = bb[n] - mean * sc;
    }
}

__global__ void bn_apply_kernel() {
    int i4 = blockIdx.x * 256 + threadIdx.x;
    int base = i4 * 4;
    int n = (base / TT_) % NN_;
    float sc = g_bns[n], sh = g_bnh[n];
    float4 v = ((const float4*)g_xln)[i4];
    float4 o;
    o.x = v.x * sc + sh; o.y = v.y * sc + sh;
    o.z = v.z * sc + sh; o.w = v.w * sc + sh;
    ((float4*)g_xbn)[i4] = o;
}

// ======================= top-k + dis prior + relu + row sums =======================
__global__ void topk_kernel(const float* __restrict__ dis) {
    int row = blockIdx.x;                 // b*N + n
    int n = row & (NN_ - 1);
    int tid = threadIdx.x;
    __shared__ float raw[256], srt[256];
    float v = g_sc[(long)row * NN_ + tid];
    raw[tid] = v; srt[tid] = v;
    __syncthreads();
    // bitonic sort ascending over 256 elements
    for (unsigned k = 2; k <= 256; k <<= 1) {
        for (unsigned j = k >> 1; j > 0; j >>= 1) {
            unsigned ixj = tid ^ j;
            if (ixj > (unsigned)tid) {
                float a = srt[tid], b2 = srt[ixj];
                bool asc = ((tid & k) == 0);
                if ((a > b2) == asc) { srt[tid] = b2; srt[ixj] = a; }
            }
            __syncthreads();
        }
    }
    float kth = srt[256 - NMAX];          // 51st largest
    __syncthreads();
    float a = (raw[tid] >= kth) ? raw[tid] : 0.f;
    a += dis[n * NN_ + tid];
    a = fmaxf(a, 0.f);
    srt[tid] = a;
    __syncthreads();
    for (int o = 128; o > 0; o >>= 1) {
        if (tid < o) srt[tid] += srt[tid + o];
        __syncthreads();
    }
    g_sc[(long)row * NN_ + tid] = a;      // overwrite scores with A
    if (tid == 0) g_dinv[row] = rsqrtf(srt[0] + 1e-10f);
}

__global__ void lscale_kernel() {
    int i4 = blockIdx.x * 256 + threadIdx.x;  // over BNN/4
    int base = i4 * 4;
    int b   = base / (NN_ * NN_);
    int rem = base % (NN_ * NN_);
    int n   = rem / NN_;
    int m   = rem % NN_;
    float dn = g_dinv[b * NN_ + n];
    const float* dm = &g_dinv[b * NN_ + m];
    float4 a = ((const float4*)g_sc)[i4];
    a.x *= dn * dm[0];
    a.y *= dn * dm[1];
    a.z *= dn * dm[2];
    a.w *= dn * dm[3];
    ((float4*)g_sc)[i4] = a;
}

// ======================= SGEMM (128x128x8 tiles, 8x8/thread) =======================
// C[z] = alpha * A[z] @ op(B[z]) + beta * D[z] (+bias) (+relu)
// A: M x K row-major. B: (NN) K x Nc row-major, (NT) Nc x K row-major.
// Requires M,Nc multiples of 128; K multiple of 8.
template<bool TRANSB>
__global__ __launch_bounds__(256, 2)
void sgemm_kernel(const float* __restrict__ A, const float* __restrict__ B,
                  const float* __restrict__ D, const float* __restrict__ bias,
                  float* __restrict__ C,
                  int M, int Nc, int Kd,
                  long sA, long sB, long sC,
                  float alpha, float beta, int relu) {
    __shared__ float As[8][132];
    __shared__ float Bs[8][132];
    int z = blockIdx.z;
    A += (long)z * sA;
    B += (long)z * sB;
    C += (long)z * sC;
    const float* Dp = D ? (D + (long)z * sC) : (const float*)0;

    int rowBase = blockIdx.y * 128;
    int colBase = blockIdx.x * 128;
    int tid = threadIdx.x;
    int tx = tid & 15, ty = tid >> 4;

    int ar = tid >> 1;
    int ac = (tid & 1) * 4;
    const float* Aptr = A + (long)(rowBase + ar) * Kd + ac;

    const float* Bptr;
    int br, bc;
    if (TRANSB) {
        br = tid >> 1; bc = (tid & 1) * 4;
        Bptr = B + (long)(colBase + br) * Kd + bc;
    } else {
        br = tid >> 5; bc = (tid & 31) * 4;
        Bptr = B + (long)br * Nc + colBase + bc;
    }

    float acc[8][8];
#pragma unroll
    for (int i = 0; i < 8; i++)
#pragma unroll
        for (int j = 0; j < 8; j++) acc[i][j] = 0.f;

    for (int kt = 0; kt < Kd; kt += 8) {
        float4 a4 = *(const float4*)(Aptr + kt);
        As[ac + 0][ar] = a4.x;
        As[ac + 1][ar] = a4.y;
        As[ac + 2][ar] = a4.z;
        As[ac + 3][ar] = a4.w;
        if (TRANSB) {
            float4 b4 = *(const float4*)(Bptr + kt);
            Bs[bc + 0][br] = b4.x;
            Bs[bc + 1][br] = b4.y;
            Bs[bc + 2][br] = b4.z;
            Bs[bc + 3][br] = b4.w;
        } else {
            float4 b4 = *(const float4*)(Bptr + (long)kt * Nc);
            *(float4*)&Bs[br][bc] = b4;
        }
        __syncthreads();
#pragma unroll
        for (int k = 0; k < 8; k++) {
            float ra[8], rb[8];
#pragma unroll
            for (int i = 0; i < 8; i++) ra[i] = As[k][ty * 8 + i];
#pragma unroll
            for (int j = 0; j < 8; j++) rb[j] = Bs[k][tx * 8 + j];
#pragma unroll
            for (int i = 0; i < 8; i++)
#pragma unroll
                for (int j = 0; j < 8; j++)
                    acc[i][j] = fmaf(ra[i], rb[j], acc[i][j]);
        }
        __syncthreads();
    }

#pragma unroll
    for (int i = 0; i < 8; i++) {
        int r = rowBase + ty * 8 + i;
        long base = (long)r * Nc + colBase + tx * 8;
#pragma unroll
        for (int j = 0; j < 8; j++) {
            float v = alpha * acc[i][j];
            if (Dp)  v += beta * Dp[base + j];
            if (bias) v += bias[colBase + tx * 8 + j];
            if (relu) v = fmaxf(v, 0.f);
            C[base + j] = v;
        }
    }
}

// ======================= launch =======================
extern "C" void kernel_launch(void* const* d_in, const int* in_sizes, int n_in,
                              void* d_out, int out_size) {
    const float* x      = (const float*)d_in[0];
    const float* dis    = (const float*)d_in[1];
    const float* ln_w   = (const float*)d_in[2];
    const float* ln_b   = (const float*)d_in[3];
    const float* bn_g   = (const float*)d_in[4];
    const float* bn_b   = (const float*)d_in[5];
    const float* li_w   = (const float*)d_in[6];
    const float* li_b   = (const float*)d_in[7];
    const float* cheb_w = (const float*)d_in[8];
    const float* cheb_b = (const float*)d_in[9];
    float* out = (float*)d_out;

    float *xln, *xbn, *xp, *sc, *tx1, *tx2;
    cudaGetSymbolAddress((void**)&xln, g_xln);
    cudaGetSymbolAddress((void**)&xbn, g_xbn);
    cudaGetSymbolAddress((void**)&xp,  g_xp);
    cudaGetSymbolAddress((void**)&sc,  g_sc);
    cudaGetSymbolAddress((void**)&tx1, g_tx1);
    cudaGetSymbolAddress((void**)&tx2, g_tx2);

    // 1. LayerNorm
    ln_stats_kernel<<<BSZ, 256>>>(x);
    ln_apply_kernel<<<BNT/4/256, 256>>>(x, ln_w, ln_b);

    // 2. BatchNorm stats + apply (independent of adjacency path)
    bn_stats_kernel<<<NN_, 256>>>(bn_g, bn_b);
    bn_apply_kernel<<<BNT/4/256, 256>>>();

    // 3. projection: xp = x_ln @ li_w^T + li_b   (NT, M=16384, N=512, K=512)
    {
        dim3 g(TT_/128, (BSZ*NN_)/128, 1);
        sgemm_kernel<true><<<g, 256>>>(xln, li_w, 0, li_b, xp,
                                       BSZ*NN_, TT_, TT_, 0, 0, 0, 1.f, 0.f, 0);
    }
    // 4. scores = xp @ xp^T (batched NT, 64 x [256x256x512])
    {
        dim3 g(NN_/128, NN_/128, BSZ);
        sgemm_kernel<true><<<g, 256>>>(xp, xp, 0, 0, sc,
                                       NN_, NN_, TT_,
                                       (long)NN_*TT_, (long)NN_*TT_, (long)NN_*NN_,
                                       1.f, 0.f, 0);
    }
    // 5. top-k threshold + dis prior + relu + degree
    topk_kernel<<<BSZ*NN_, 256>>>(dis);
    // 6. L = D^-1/2 A D^-1/2 (in place)
    lscale_kernel<<<BNN/4/256, 256>>>();

    // 7. Tx1 = L @ x_bn  (batched NN, K=256)
    {
        dim3 g(TT_/128, NN_/128, BSZ);
        sgemm_kernel<false><<<g, 256>>>(sc, xbn, 0, 0, tx1,
                                        NN_, TT_, NN_,
                                        (long)NN_*NN_, (long)NN_*TT_, (long)NN_*TT_,
                                        1.f, 0.f, 0);
    }
    // 8. Tx2 = 2*L @ Tx1 - Tx0
    {
        dim3 g(TT_/128, NN_/128, BSZ);
        sgemm_kernel<false><<<g, 256>>>(sc, tx1, xbn, 0, tx2,
                                        NN_, TT_, NN_,
                                        (long)NN_*NN_, (long)NN_*TT_, (long)NN_*TT_,
                                        2.f, -1.f, 0);
    }
    // 9. out = relu(Tx0@W0 + Tx1@W1 + Tx2@W2 + cheb_b)
    {
        dim3 g(TT_/128, (BSZ*NN_)/128, 1);
        sgemm_kernel<false><<<g, 256>>>(xbn, cheb_w, 0, 0, out,
                                        BSZ*NN_, TT_, TT_, 0, 0, 0, 1.f, 0.f, 0);
        sgemm_kernel<false><<<g, 256>>>(tx1, cheb_w + TT_*TT_, out, 0, out,
                                        BSZ*NN_, TT_, TT_, 0, 0, 0, 1.f, 1.f, 0);
        sgemm_kernel<false><<<g, 256>>>(tx2, cheb_w + 2*TT_*TT_, out, cheb_b, out,
                                        BSZ*NN_, TT_, TT_, 0, 0, 0, 1.f, 1.f, 1);
    }
}

// round 3
// speedup vs baseline: 1.4159x; 1.4159x over previous
#include <cuda_runtime.h>

// Problem constants
#define BSZ 64
#define NN_ 256
#define TT_ 512
#define NT_ (NN_*TT_)          // 131072
#define BNT (BSZ*NN_*TT_)      // 8388608
#define BNN (BSZ*NN_*NN_)      // 4194304
#define NMAX 51                // 256/5
#define KCAT 1536              // 3*T concatenated Chebyshev inputs

// -------- scratch (device globals; no allocation allowed) --------
__device__ float g_xln[BNT];
__device__ float g_xp [BNT];
__device__ float g_sc [BNN];                  // scores -> A -> L (in place)
__device__ float g_cat[(long)BSZ*NN_*KCAT];   // [Tx0 | Tx1 | Tx2] per row
__device__ float g_mu  [BSZ];
__device__ float g_rstd[BSZ];
__device__ float g_bns [NN_];
__device__ float g_bnh [NN_];
__device__ float g_dinv[BSZ*NN_];

// ======================= LayerNorm =======================
__global__ void ln_stats_kernel(const float* __restrict__ x) {
    int b = blockIdx.x;
    const float4* xb = (const float4*)(x + (long)b * NT_);
    float s = 0.f, q = 0.f;
    for (int i = threadIdx.x; i < NT_/4; i += 256) {
        float4 v = xb[i];
        s += v.x + v.y + v.z + v.w;
        q += v.x*v.x + v.y*v.y + v.z*v.z + v.w*v.w;
    }
    __shared__ float ss[256], sq[256];
    ss[threadIdx.x] = s; sq[threadIdx.x] = q;
    __syncthreads();
    for (int o = 128; o > 0; o >>= 1) {
        if (threadIdx.x < o) { ss[threadIdx.x] += ss[threadIdx.x+o]; sq[threadIdx.x] += sq[threadIdx.x+o]; }
        __syncthreads();
    }
    if (threadIdx.x == 0) {
        float mu  = ss[0] / (float)NT_;
        float var = sq[0] / (float)NT_ - mu * mu;
        g_mu[b] = mu;
        g_rstd[b] = rsqrtf(var + 1e-5f);
    }
}

__global__ void ln_apply_kernel(const float* __restrict__ x,
                                const float* __restrict__ lw,
                                const float* __restrict__ lb) {
    int i4 = blockIdx.x * 256 + threadIdx.x;      // over BNT/4
    int base = i4 * 4;
    int b  = base / NT_;
    int nt4 = (base % NT_) / 4;
    float mu = g_mu[b], rs = g_rstd[b];
    float4 v = ((const float4*)x)[i4];
    float4 w = ((const float4*)lw)[nt4];
    float4 bb = ((const float4*)lb)[nt4];
    float4 o;
    o.x = (v.x - mu) * rs * w.x + bb.x;
    o.y = (v.y - mu) * rs * w.y + bb.y;
    o.z = (v.z - mu) * rs * w.z + bb.z;
    o.w = (v.w - mu) * rs * w.w + bb.w;
    ((float4*)g_xln)[i4] = o;
}

// ======================= BatchNorm over (b,t) per node =======================
__global__ void bn_stats_kernel(const float* __restrict__ bg,
                                const float* __restrict__ bb) {
    int n = blockIdx.x;
    float s = 0.f, q = 0.f;
    for (int i = threadIdx.x; i < (BSZ*TT_)/4; i += 256) {
        int base = i * 4;
        int b = base / TT_;
        int t = base % TT_;
        float4 v = *(const float4*)&g_xln[((long)b * NN_ + n) * TT_ + t];
        s += v.x + v.y + v.z + v.w;
        q += v.x*v.x + v.y*v.y + v.z*v.z + v.w*v.w;
    }
    __shared__ float ss[256], sq[256];
    ss[threadIdx.x] = s; sq[threadIdx.x] = q;
    __syncthreads();
    for (int o = 128; o > 0; o >>= 1) {
        if (threadIdx.x < o) { ss[threadIdx.x] += ss[threadIdx.x+o]; sq[threadIdx.x] += sq[threadIdx.x+o]; }
        __syncthreads();
    }
    if (threadIdx.x == 0) {
        float cnt  = (float)(BSZ * TT_);
        float mean = ss[0] / cnt;
        float var  = sq[0] / cnt - mean * mean;
        float sc   = bg[n] * rsqrtf(var + 1e-5f);
        g_bns[n] = sc;
        g_bnh[n] = bb[n] - mean * sc;
    }
}

// writes x_bn into g_cat slot 0 (row stride KCAT)
__global__ void bn_apply_kernel() {
    int i4 = blockIdx.x * 256 + threadIdx.x;
    int base = i4 * 4;
    int row = base / TT_;            // b*N + n
    int col = base % TT_;
    int n = row & (NN_ - 1);
    float sc = g_bns[n], sh = g_bnh[n];
    float4 v = ((const float4*)g_xln)[i4];
    float4 o;
    o.x = v.x * sc + sh; o.y = v.y * sc + sh;
    o.z = v.z * sc + sh; o.w = v.w * sc + sh;
    *(float4*)&g_cat[(long)row * KCAT + col] = o;
}

// ======================= top-k + dis prior + relu + row sums =======================
__global__ void topk_kernel(const float* __restrict__ dis) {
    int row = blockIdx.x;                 // b*N + n
    int n = row & (NN_ - 1);
    int tid = threadIdx.x;
    __shared__ float raw[256], srt[256];
    float v = g_sc[(long)row * NN_ + tid];
    raw[tid] = v; srt[tid] = v;
    __syncthreads();
    for (unsigned k = 2; k <= 256; k <<= 1) {
        for (unsigned j = k >> 1; j > 0; j >>= 1) {
            unsigned ixj = tid ^ j;
            if (ixj > (unsigned)tid) {
                float a = srt[tid], b2 = srt[ixj];
                bool asc = ((tid & k) == 0);
                if ((a > b2) == asc) { srt[tid] = b2; srt[ixj] = a; }
            }
            __syncthreads();
        }
    }
    float kth = srt[256 - NMAX];          // 51st largest
    __syncthreads();
    float a = (raw[tid] >= kth) ? raw[tid] : 0.f;
    a += dis[n * NN_ + tid];
    a = fmaxf(a, 0.f);
    srt[tid] = a;
    __syncthreads();
    for (int o = 128; o > 0; o >>= 1) {
        if (tid < o) srt[tid] += srt[tid + o];
        __syncthreads();
    }
    g_sc[(long)row * NN_ + tid] = a;      // overwrite scores with A
    if (tid == 0) g_dinv[row] = rsqrtf(srt[0] + 1e-10f);
}

__global__ void lscale_kernel() {
    int i4 = blockIdx.x * 256 + threadIdx.x;  // over BNN/4
    int base = i4 * 4;
    int b   = base / (NN_ * NN_);
    int rem = base % (NN_ * NN_);
    int n   = rem / NN_;
    int m   = rem % NN_;
    float dn = g_dinv[b * NN_ + n];
    const float* dm = &g_dinv[b * NN_ + m];
    float4 a = ((const float4*)g_sc)[i4];
    a.x *= dn * dm[0];
    a.y *= dn * dm[1];
    a.z *= dn * dm[2];
    a.w *= dn * dm[3];
    ((float4*)g_sc)[i4] = a;
}

// ======================= 3xTF32 MMA GEMM =======================
__device__ __forceinline__ unsigned to_tf32(float v) {
    unsigned r;
    asm("cvt.rna.tf32.f32 %0, %1;" : "=r"(r) : "f"(v));
    return r;
}

__device__ __forceinline__ void split_tf32(float v, unsigned& hi, unsigned& lo) {
    hi = to_tf32(v);
    lo = to_tf32(v - __uint_as_float(hi));
}

__device__ __forceinline__ void mma_tf32(float* c, const unsigned* a,
                                         unsigned b0, unsigned b1) {
    asm volatile(
        "mma.sync.aligned.m16n8k8.row.col.f32.tf32.tf32.f32 "
        "{%0,%1,%2,%3}, {%4,%5,%6,%7}, {%8,%9}, {%0,%1,%2,%3};"
        : "+f"(c[0]), "+f"(c[1]), "+f"(c[2]), "+f"(c[3])
        : "r"(a[0]), "r"(a[1]), "r"(a[2]), "r"(a[3]), "r"(b0), "r"(b1));
}

// C = alpha*A@op(B) + beta*D (+bias) (+relu). Tiles 128x128, K-chunk 8, 3xTF32.
// A: MxK row-major (ldA). B: TRANSB ? NxK row-major : KxN row-major (ldB).
// M, Nc multiples of 128; Kd multiple of 8.
template<bool TRANSB>
__global__ __launch_bounds__(256, 2)
void gemm3_kernel(const float* __restrict__ A, const float* __restrict__ B,
                  const float* __restrict__ D, const float* __restrict__ bias,
                  float* __restrict__ C,
                  int M, int Nc, int Kd, int ldA, int ldB, int ldC,
                  long sA, long sB, long sC,
                  float alpha, float beta, int relu) {
    __shared__ unsigned Ah[2][128][12];   // [m][k] pad 12 -> conflict-free frags
    __shared__ unsigned Al[2][128][12];
    __shared__ unsigned Bh[2][8][136];    // [k][n] pad 136 -> conflict-free frags
    __shared__ unsigned Bl[2][8][136];

    int z = blockIdx.z;
    A += (long)z * sA;
    B += (long)z * sB;
    C += (long)z * sC;
    const float* Dp = D ? (D + (long)z * sC) : (const float*)0;

    int rowBase = blockIdx.y * 128;
    int colBase = blockIdx.x * 128;
    int tid = threadIdx.x;
    int lane = tid & 31;
    int warp = tid >> 5;
    int g  = lane >> 2;       // group id (row within m8 / col within n8)
    int t4 = lane & 3;        // thread in group (k index)
    int mW = (warp >> 1) * 32;   // warp m offset (4 warps along M)
    int nW = (warp & 1) * 64;    // warp n offset (2 warps along N)

    float acc[2][8][4];
#pragma unroll
    for (int t = 0; t < 2; t++)
#pragma unroll
        for (int j = 0; j < 8; j++)
#pragma unroll
            for (int c = 0; c < 4; c++) acc[t][j][c] = 0.f;

    float4 pa, pb;
    int nCh = Kd >> 3;

    // A tile 128x8: thread -> row tid>>1, col (tid&1)*4
    int arr = tid >> 1, arc = (tid & 1) * 4;
    // B tile: TRANSB n-major (row tid>>1, k (tid&1)*4); else k tid>>5, n (tid&31)*4
    int bn  = tid >> 1, bkc = (tid & 1) * 4;
    int bk  = tid >> 5, bn4 = tid & 31;

#define LDG_CHUNK(KT)                                                          \
    {                                                                          \
        pa = *(const float4*)(A + (long)(rowBase + arr) * ldA + (KT) + arc);   \
        if (TRANSB)                                                            \
            pb = *(const float4*)(B + (long)(colBase + bn) * ldB + (KT) + bkc);\
        else                                                                   \
            pb = *(const float4*)(B + (long)((KT) + bk) * ldB + colBase + bn4 * 4); \
    }

#define STS_CHUNK(BUF)                                                         \
    {                                                                          \
        uint4 h4, l4;                                                          \
        split_tf32(pa.x, h4.x, l4.x); split_tf32(pa.y, h4.y, l4.y);            \
        split_tf32(pa.z, h4.z, l4.z); split_tf32(pa.w, h4.w, l4.w);            \
        *(uint4*)&Ah[BUF][arr][arc] = h4;                                      \
        *(uint4*)&Al[BUF][arr][arc] = l4;                                      \
        split_tf32(pb.x, h4.x, l4.x); split_tf32(pb.y, h4.y, l4.y);            \
        split_tf32(pb.z, h4.z, l4.z); split_tf32(pb.w, h4.w, l4.w);            \
        if (TRANSB) {                                                          \
            Bh[BUF][bkc + 0][bn] = h4.x; Bh[BUF][bkc + 1][bn] = h4.y;          \
            Bh[BUF][bkc + 2][bn] = h4.z; Bh[BUF][bkc + 3][bn] = h4.w;          \
            Bl[BUF][bkc + 0][bn] = l4.x; Bl[BUF][bkc + 1][bn] = l4.y;          \
            Bl[BUF][bkc + 2][bn] = l4.z; Bl[BUF][bkc + 3][bn] = l4.w;          \
        } else {                                                               \
            *(uint4*)&Bh[BUF][bk][bn4 * 4] = h4;                               \
            *(uint4*)&Bl[BUF][bk][bn4 * 4] = l4;                               \
        }                                                                      \
    }

    LDG_CHUNK(0)
    STS_CHUNK(0)
    __syncthreads();

    for (int ch = 0; ch < nCh; ch++) {
        int cur = ch & 1;
        if (ch + 1 < nCh) LDG_CHUNK((ch + 1) << 3)

        unsigned ah[2][4], al[2][4];
#pragma unroll
        for (int t = 0; t < 2; t++) {
            int mr = mW + t * 16 + g;
            ah[t][0] = Ah[cur][mr    ][t4];
            ah[t][1] = Ah[cur][mr + 8][t4];
            ah[t][2] = Ah[cur][mr    ][t4 + 4];
            ah[t][3] = Ah[cur][mr + 8][t4 + 4];
            al[t][0] = Al[cur][mr    ][t4];
            al[t][1] = Al[cur][mr + 8][t4];
            al[t][2] = Al[cur][mr    ][t4 + 4];
            al[t][3] = Al[cur][mr + 8][t4 + 4];
        }
#pragma unroll
        for (int j = 0; j < 8; j++) {
            int nc = nW + j * 8 + g;
            unsigned b0h = Bh[cur][t4    ][nc];
            unsigned b1h = Bh[cur][t4 + 4][nc];
            unsigned b0l = Bl[cur][t4    ][nc];
            unsigned b1l = Bl[cur][t4 + 4][nc];
#pragma unroll
            for (int t = 0; t < 2; t++) {
                mma_tf32(acc[t][j], ah[t], b0h, b1h);  // hi*hi
                mma_tf32(acc[t][j], al[t], b0h, b1h);  // lo*hi
                mma_tf32(acc[t][j], ah[t], b0l, b1l);  // hi*lo
            }
        }

        if (ch + 1 < nCh) STS_CHUNK(cur ^ 1)
        __syncthreads();
    }

    // ---- epilogue ----
#pragma unroll
    for (int t = 0; t < 2; t++) {
#pragma unroll
        for (int j = 0; j < 8; j++) {
            int r0 = rowBase + mW + t * 16 + g;
            int c0 = colBase + nW + j * 8 + t4 * 2;
#pragma unroll
            for (int rr = 0; rr < 2; rr++) {
                int r = r0 + rr * 8;
                long base = (long)r * ldC + c0;
#pragma unroll
                for (int cc = 0; cc < 2; cc++) {
                    float v = alpha * acc[t][j][rr * 2 + cc];
                    if (Dp)   v += beta * Dp[base + cc];
                    if (bias) v += bias[c0 + cc];
                    if (relu) v = fmaxf(v, 0.f);
                    C[base + cc] = v;
                }
            }
        }
    }
#undef LDG_CHUNK
#undef STS_CHUNK
}

// ======================= launch =======================
extern "C" void kernel_launch(void* const* d_in, const int* in_sizes, int n_in,
                              void* d_out, int out_size) {
    const float* x      = (const float*)d_in[0];
    const float* dis    = (const float*)d_in[1];
    const float* ln_w   = (const float*)d_in[2];
    const float* ln_b   = (const float*)d_in[3];
    const float* bn_g   = (const float*)d_in[4];
    const float* bn_b   = (const float*)d_in[5];
    const float* li_w   = (const float*)d_in[6];
    const float* li_b   = (const float*)d_in[7];
    const float* cheb_w = (const float*)d_in[8];
    const float* cheb_b = (const float*)d_in[9];
    float* out = (float*)d_out;

    float *xln, *xp, *sc, *cat;
    cudaGetSymbolAddress((void**)&xln, g_xln);
    cudaGetSymbolAddress((void**)&xp,  g_xp);
    cudaGetSymbolAddress((void**)&sc,  g_sc);
    cudaGetSymbolAddress((void**)&cat, g_cat);

    // 1. LayerNorm
    ln_stats_kernel<<<BSZ, 256>>>(x);
    ln_apply_kernel<<<BNT/4/256, 256>>>(x, ln_w, ln_b);

    // 2. BatchNorm (writes x_bn into cat slot 0)
    bn_stats_kernel<<<NN_, 256>>>(bn_g, bn_b);
    bn_apply_kernel<<<BNT/4/256, 256>>>();

    // 3. xp = x_ln @ li_w^T + li_b   (M=16384, N=512, K=512, TRANSB)
    {
        dim3 g(TT_/128, (BSZ*NN_)/128, 1);
        gemm3_kernel<true><<<g, 256>>>(xln, li_w, 0, li_b, xp,
            BSZ*NN_, TT_, TT_, TT_, TT_, TT_, 0, 0, 0, 1.f, 0.f, 0);
    }
    // 4. scores = xp @ xp^T (batched 64 x [256x256x512], TRANSB)
    {
        dim3 g(NN_/128, NN_/128, BSZ);
        gemm3_kernel<true><<<g, 256>>>(xp, xp, 0, 0, sc,
            NN_, NN_, TT_, TT_, TT_, NN_,
            (long)NN_*TT_, (long)NN_*TT_, (long)NN_*NN_, 1.f, 0.f, 0);
    }
    // 5. top-k threshold + dis prior + relu + degree
    topk_kernel<<<BSZ*NN_, 256>>>(dis);
    // 6. L = D^-1/2 A D^-1/2 (in place)
    lscale_kernel<<<BNN/4/256, 256>>>();

    // 7. Tx1 = L @ Tx0  -> cat slot 1
    {
        dim3 g(TT_/128, NN_/128, BSZ);
        gemm3_kernel<false><<<g, 256>>>(sc, cat, 0, 0, cat + TT_,
            NN_, TT_, NN_, NN_, KCAT, KCAT,
            (long)NN_*NN_, (long)NN_*KCAT, (long)NN_*KCAT, 1.f, 0.f, 0);
    }
    // 8. Tx2 = 2*L @ Tx1 - Tx0 -> cat slot 2
    {
        dim3 g(TT_/128, NN_/128, BSZ);
        gemm3_kernel<false><<<g, 256>>>(sc, cat + TT_, cat, 0, cat + 2*TT_,
            NN_, TT_, NN_, NN_, KCAT, KCAT,
            (long)NN_*NN_, (long)NN_*KCAT, (long)NN_*KCAT, 2.f, -1.f, 0);
    }
    // 9. out = relu(cat @ cheb_w_flat + cheb_b)  (M=16384, N=512, K=1536)
    {
        dim3 g(TT_/128, (BSZ*NN_)/128, 1);
        gemm3_kernel<false><<<g, 256>>>(cat, cheb_w, 0, cheb_b, out,
            BSZ*NN_, TT_, KCAT, KCAT, TT_, TT_, 0, 0, 0, 1.f, 0.f, 1);
    }
}

// round 4
// speedup vs baseline: 2.2389x; 1.5813x over previous
#include <cuda_runtime.h>
#include <cuda_bf16.h>

// Problem constants
#define BSZ 64
#define NN_ 256
#define TT_ 512
#define NT_ (NN_*TT_)          // 131072
#define BNT (BSZ*NN_*TT_)      // 8388608
#define BNN (BSZ*NN_*NN_)      // 4194304
#define NMAX 51                // 256/5
#define KCAT 1536              // 3*T concatenated Chebyshev inputs

// -------- scratch (device globals; no allocation allowed) --------
__device__ float g_xln[BNT];
__device__ float g_xp [BNT];
__device__ float g_sc [BNN];                  // scores -> A -> L (in place)
__device__ float g_cat[(long)BSZ*NN_*KCAT];   // [Tx0 | Tx1 | Tx2] per row
__device__ float g_mu  [BSZ];
__device__ float g_rstd[BSZ];
__device__ float g_bns [NN_];
__device__ float g_bnh [NN_];
__device__ float g_dinv[BSZ*NN_];

// ======================= LayerNorm =======================
__global__ void ln_stats_kernel(const float* __restrict__ x) {
    int b = blockIdx.x;
    const float4* xb = (const float4*)(x + (long)b * NT_);
    float s = 0.f, q = 0.f;
    for (int i = threadIdx.x; i < NT_/4; i += 256) {
        float4 v = xb[i];
        s += v.x + v.y + v.z + v.w;
        q += v.x*v.x + v.y*v.y + v.z*v.z + v.w*v.w;
    }
    __shared__ float ss[256], sq[256];
    ss[threadIdx.x] = s; sq[threadIdx.x] = q;
    __syncthreads();
    for (int o = 128; o > 0; o >>= 1) {
        if (threadIdx.x < o) { ss[threadIdx.x] += ss[threadIdx.x+o]; sq[threadIdx.x] += sq[threadIdx.x+o]; }
        __syncthreads();
    }
    if (threadIdx.x == 0) {
        float mu  = ss[0] / (float)NT_;
        float var = sq[0] / (float)NT_ - mu * mu;
        g_mu[b] = mu;
        g_rstd[b] = rsqrtf(var + 1e-5f);
    }
}

__global__ void ln_apply_kernel(const float* __restrict__ x,
                                const float* __restrict__ lw,
                                const float* __restrict__ lb) {
    int i4 = blockIdx.x * 256 + threadIdx.x;      // over BNT/4
    int base = i4 * 4;
    int b  = base / NT_;
    int nt4 = (base % NT_) / 4;
    float mu = g_mu[b], rs = g_rstd[b];
    float4 v = ((const float4*)x)[i4];
    float4 w = ((const float4*)lw)[nt4];
    float4 bb = ((const float4*)lb)[nt4];
    float4 o;
    o.x = (v.x - mu) * rs * w.x + bb.x;
    o.y = (v.y - mu) * rs * w.y + bb.y;
    o.z = (v.z - mu) * rs * w.z + bb.z;
    o.w = (v.w - mu) * rs * w.w + bb.w;
    ((float4*)g_xln)[i4] = o;
}

// ======================= BatchNorm over (b,t) per node =======================
__global__ void bn_stats_kernel(const float* __restrict__ bg,
                                const float* __restrict__ bb) {
    int n = blockIdx.x;
    float s = 0.f, q = 0.f;
    for (int i = threadIdx.x; i < (BSZ*TT_)/4; i += 256) {
        int base = i * 4;
        int b = base / TT_;
        int t = base % TT_;
        float4 v = *(const float4*)&g_xln[((long)b * NN_ + n) * TT_ + t];
        s += v.x + v.y + v.z + v.w;
        q += v.x*v.x + v.y*v.y + v.z*v.z + v.w*v.w;
    }
    __shared__ float ss[256], sq[256];
    ss[threadIdx.x] = s; sq[threadIdx.x] = q;
    __syncthreads();
    for (int o = 128; o > 0; o >>= 1) {
        if (threadIdx.x < o) { ss[threadIdx.x] += ss[threadIdx.x+o]; sq[threadIdx.x] += sq[threadIdx.x+o]; }
        __syncthreads();
    }
    if (threadIdx.x == 0) {
        float cnt  = (float)(BSZ * TT_);
        float mean = ss[0] / cnt;
        float var  = sq[0] / cnt - mean * mean;
        float sc   = bg[n] * rsqrtf(var + 1e-5f);
        g_bns[n] = sc;
        g_bnh[n] = bb[n] - mean * sc;
    }
}

// writes x_bn into g_cat slot 0 (row stride KCAT)
__global__ void bn_apply_kernel() {
    int i4 = blockIdx.x * 256 + threadIdx.x;
    int base = i4 * 4;
    int row = base / TT_;            // b*N + n
    int col = base % TT_;
    int n = row & (NN_ - 1);
    float sc = g_bns[n], sh = g_bnh[n];
    float4 v = ((const float4*)g_xln)[i4];
    float4 o;
    o.x = v.x * sc + sh; o.y = v.y * sc + sh;
    o.z = v.z * sc + sh; o.w = v.w * sc + sh;
    *(float4*)&g_cat[(long)row * KCAT + col] = o;
}

// ======================= top-k + dis prior + relu + row sums =======================
__global__ void topk_kernel(const float* __restrict__ dis) {
    int row = blockIdx.x;                 // b*N + n
    int n = row & (NN_ - 1);
    int tid = threadIdx.x;
    __shared__ float raw[256], srt[256];
    float v = g_sc[(long)row * NN_ + tid];
    raw[tid] = v; srt[tid] = v;
    __syncthreads();
    for (unsigned k = 2; k <= 256; k <<= 1) {
        for (unsigned j = k >> 1; j > 0; j >>= 1) {
            unsigned ixj = tid ^ j;
            if (ixj > (unsigned)tid) {
                float a = srt[tid], b2 = srt[ixj];
                bool asc = ((tid & k) == 0);
                if ((a > b2) == asc) { srt[tid] = b2; srt[ixj] = a; }
            }
            __syncthreads();
        }
    }
    float kth = srt[256 - NMAX];          // 51st largest
    __syncthreads();
    float a = (raw[tid] >= kth) ? raw[tid] : 0.f;
    a += dis[n * NN_ + tid];
    a = fmaxf(a, 0.f);
    srt[tid] = a;
    __syncthreads();
    for (int o = 128; o > 0; o >>= 1) {
        if (tid < o) srt[tid] += srt[tid + o];
        __syncthreads();
    }
    g_sc[(long)row * NN_ + tid] = a;      // overwrite scores with A
    if (tid == 0) g_dinv[row] = rsqrtf(srt[0] + 1e-10f);
}

__global__ void lscale_kernel() {
    int i4 = blockIdx.x * 256 + threadIdx.x;  // over BNN/4
    int base = i4 * 4;
    int b   = base / (NN_ * NN_);
    int rem = base % (NN_ * NN_);
    int n   = rem / NN_;
    int m   = rem % NN_;
    float dn = g_dinv[b * NN_ + n];
    const float* dm = &g_dinv[b * NN_ + m];
    float4 a = ((const float4*)g_sc)[i4];
    a.x *= dn * dm[0];
    a.y *= dn * dm[1];
    a.z *= dn * dm[2];
    a.w *= dn * dm[3];
    ((float4*)g_sc)[i4] = a;
}

// ======================= bf16 2-split / 3-product MMA GEMM =======================
__device__ __forceinline__ unsigned pack_bf2(float a, float b) {
    __nv_bfloat162 h = __floats2bfloat162_rn(a, b);
    return *reinterpret_cast<unsigned*>(&h);
}

// split v -> hi + lo (both bf16); returns residual lo as float for packing
__device__ __forceinline__ void split_bf(float v, float& hi, float& lo) {
    __nv_bfloat16 h = __float2bfloat16_rn(v);
    hi = __bfloat162float(h);
    lo = v - hi;
}

__device__ __forceinline__ void mma_bf16(float* c, const unsigned* a,
                                         unsigned b0, unsigned b1) {
    asm volatile(
        "mma.sync.aligned.m16n8k16.row.col.f32.bf16.bf16.f32 "
        "{%0,%1,%2,%3}, {%4,%5,%6,%7}, {%8,%9}, {%0,%1,%2,%3};"
        : "+f"(c[0]), "+f"(c[1]), "+f"(c[2]), "+f"(c[3])
        : "r"(a[0]), "r"(a[1]), "r"(a[2]), "r"(a[3]), "r"(b0), "r"(b1));
}

// C = alpha*A@op(B) + beta*D (+bias) (+relu). Tiles 128x128, K-chunk 16.
// A: MxK row-major (ldA). B: TRANSB ? NxK row-major : KxN row-major (ldB).
// M, Nc multiples of 128; Kd multiple of 16.
// smem: hi/lo tiles stored as k-pair-packed bf16x2 words, row stride 12 words.
template<bool TRANSB>
__global__ __launch_bounds__(256, 2)
void gemm_bf3_kernel(const float* __restrict__ A, const float* __restrict__ B,
                     const float* __restrict__ D, const float* __restrict__ bias,
                     float* __restrict__ C,
                     int M, int Nc, int Kd, int ldA, int ldB, int ldC,
                     long sA, long sB, long sC,
                     float alpha, float beta, int relu) {
    __shared__ __align__(16) unsigned Ah[2][128][12];
    __shared__ __align__(16) unsigned Al[2][128][12];
    __shared__ __align__(16) unsigned Bh[2][128][12];
    __shared__ __align__(16) unsigned Bl[2][128][12];

    int z = blockIdx.z;
    A += (long)z * sA;
    B += (long)z * sB;
    C += (long)z * sC;
    const float* Dp = D ? (D + (long)z * sC) : (const float*)0;

    int rowBase = blockIdx.y * 128;
    int colBase = blockIdx.x * 128;
    int tid = threadIdx.x;
    int lane = tid & 31;
    int warp = tid >> 5;
    int g  = lane >> 2;          // group id (row within m8 / col within n8)
    int t4 = lane & 3;           // thread-in-group (k-pair index)
    int mW = (warp >> 1) * 32;   // warp m offset (4 warps along M)
    int nW = (warp & 1) * 64;    // warp n offset (2 warps along N)

    float acc[2][8][4];
#pragma unroll
    for (int t = 0; t < 2; t++)
#pragma unroll
        for (int j = 0; j < 8; j++)
#pragma unroll
            for (int c = 0; c < 4; c++) acc[t][j][c] = 0.f;

    // loader indexing
    int arow = tid >> 1, akc = (tid & 1) * 8;       // A: 2 float4 along k
    int bnr  = tid >> 1, bkc = (tid & 1) * 8;       // B TRANSB: 2 float4 along k
    int bng  = tid & 127, bkh = tid >> 7;           // B NN: 8 scalar gathers

    float pa[8], pb[8];
    int nCh = Kd >> 4;

#define LDG_CHUNK(KT)                                                          \
    {                                                                          \
        float4 v0 = *(const float4*)(A + (long)(rowBase + arow) * ldA + (KT) + akc);      \
        float4 v1 = *(const float4*)(A + (long)(rowBase + arow) * ldA + (KT) + akc + 4);  \
        pa[0]=v0.x; pa[1]=v0.y; pa[2]=v0.z; pa[3]=v0.w;                        \
        pa[4]=v1.x; pa[5]=v1.y; pa[6]=v1.z; pa[7]=v1.w;                        \
        if (TRANSB) {                                                          \
            float4 w0 = *(const float4*)(B + (long)(colBase + bnr) * ldB + (KT) + bkc);      \
            float4 w1 = *(const float4*)(B + (long)(colBase + bnr) * ldB + (KT) + bkc + 4);  \
            pb[0]=w0.x; pb[1]=w0.y; pb[2]=w0.z; pb[3]=w0.w;                    \
            pb[4]=w1.x; pb[5]=w1.y; pb[6]=w1.z; pb[7]=w1.w;                    \
        } else {                                                               \
            _Pragma("unroll")                                                  \
            for (int i = 0; i < 8; i++)                                        \
                pb[i] = B[(long)((KT) + bkh * 8 + i) * ldB + colBase + bng];   \
        }                                                                      \
    }

#define STS_CHUNK(BUF)                                                         \
    {                                                                          \
        float h[8], l[8];                                                      \
        uint4 hh, ll;                                                          \
        _Pragma("unroll")                                                      \
        for (int i = 0; i < 8; i++) split_bf(pa[i], h[i], l[i]);               \
        hh.x = pack_bf2(h[0],h[1]); hh.y = pack_bf2(h[2],h[3]);                \
        hh.z = pack_bf2(h[4],h[5]); hh.w = pack_bf2(h[6],h[7]);                \
        ll.x = pack_bf2(l[0],l[1]); ll.y = pack_bf2(l[2],l[3]);                \
        ll.z = pack_bf2(l[4],l[5]); ll.w = pack_bf2(l[6],l[7]);                \
        *(uint4*)&Ah[BUF][arow][(tid & 1) * 4] = hh;                           \
        *(uint4*)&Al[BUF][arow][(tid & 1) * 4] = ll;                           \
        _Pragma("unroll")                                                      \
        for (int i = 0; i < 8; i++) split_bf(pb[i], h[i], l[i]);               \
        hh.x = pack_bf2(h[0],h[1]); hh.y = pack_bf2(h[2],h[3]);                \
        hh.z = pack_bf2(h[4],h[5]); hh.w = pack_bf2(h[6],h[7]);                \
        ll.x = pack_bf2(l[0],l[1]); ll.y = pack_bf2(l[2],l[3]);                \
        ll.z = pack_bf2(l[4],l[5]); ll.w = pack_bf2(l[6],l[7]);                \
        if (TRANSB) {                                                          \
            *(uint4*)&Bh[BUF][bnr][(tid & 1) * 4] = hh;                        \
            *(uint4*)&Bl[BUF][bnr][(tid & 1) * 4] = ll;                        \
        } else {                                                               \
            *(uint4*)&Bh[BUF][bng][bkh * 4] = hh;                              \
            *(uint4*)&Bl[BUF][bng][bkh * 4] = ll;                              \
        }                                                                      \
    }

    LDG_CHUNK(0)
    STS_CHUNK(0)
    __syncthreads();

    for (int ch = 0; ch < nCh; ch++) {
        int cur = ch & 1;
        if (ch + 1 < nCh) LDG_CHUNK((ch + 1) << 4)

        unsigned ah[2][4], al[2][4];
#pragma unroll
        for (int t = 0; t < 2; t++) {
            int mr = mW + t * 16 + g;
            ah[t][0] = Ah[cur][mr    ][t4];
            ah[t][1] = Ah[cur][mr + 8][t4];
            ah[t][2] = Ah[cur][mr    ][t4 + 4];
            ah[t][3] = Ah[cur][mr + 8][t4 + 4];
            al[t][0] = Al[cur][mr    ][t4];
            al[t][1] = Al[cur][mr + 8][t4];
            al[t][2] = Al[cur][mr    ][t4 + 4];
            al[t][3] = Al[cur][mr + 8][t4 + 4];
        }
#pragma unroll
        for (int j = 0; j < 8; j++) {
            int nc = nW + j * 8 + g;
            unsigned b0h = Bh[cur][nc][t4];
            unsigned b1h = Bh[cur][nc][t4 + 4];
            unsigned b0l = Bl[cur][nc][t4];
            unsigned b1l = Bl[cur][nc][t4 + 4];
#pragma unroll
            for (int t = 0; t < 2; t++) {
                mma_bf16(acc[t][j], ah[t], b0h, b1h);  // hi*hi
                mma_bf16(acc[t][j], al[t], b0h, b1h);  // lo*hi
                mma_bf16(acc[t][j], ah[t], b0l, b1l);  // hi*lo
            }
        }

        if (ch + 1 < nCh) STS_CHUNK(cur ^ 1)
        __syncthreads();
    }

    // ---- epilogue ----
#pragma unroll
    for (int t = 0; t < 2; t++) {
#pragma unroll
        for (int j = 0; j < 8; j++) {
            int r0 = rowBase + mW + t * 16 + g;
            int c0 = colBase + nW + j * 8 + t4 * 2;
#pragma unroll
            for (int rr = 0; rr < 2; rr++) {
                int r = r0 + rr * 8;
                long base = (long)r * ldC + c0;
#pragma unroll
                for (int cc = 0; cc < 2; cc++) {
                    float v = alpha * acc[t][j][rr * 2 + cc];
                    if (Dp)   v += beta * Dp[base + cc];
                    if (bias) v += bias[c0 + cc];
                    if (relu) v = fmaxf(v, 0.f);
                    C[base + cc] = v;
                }
            }
        }
    }
#undef LDG_CHUNK
#undef STS_CHUNK
}

// ======================= launch =======================
extern "C" void kernel_launch(void* const* d_in, const int* in_sizes, int n_in,
                              void* d_out, int out_size) {
    const float* x      = (const float*)d_in[0];
    const float* dis    = (const float*)d_in[1];
    const float* ln_w   = (const float*)d_in[2];
    const float* ln_b   = (const float*)d_in[3];
    const float* bn_g   = (const float*)d_in[4];
    const float* bn_b   = (const float*)d_in[5];
    const float* li_w   = (const float*)d_in[6];
    const float* li_b   = (const float*)d_in[7];
    const float* cheb_w = (const float*)d_in[8];
    const float* cheb_b = (const float*)d_in[9];
    float* out = (float*)d_out;

    float *xln, *xp, *sc, *cat;
    cudaGetSymbolAddress((void**)&xln, g_xln);
    cudaGetSymbolAddress((void**)&xp,  g_xp);
    cudaGetSymbolAddress((void**)&sc,  g_sc);
    cudaGetSymbolAddress((void**)&cat, g_cat);

    // 1. LayerNorm
    ln_stats_kernel<<<BSZ, 256>>>(x);
    ln_apply_kernel<<<BNT/4/256, 256>>>(x, ln_w, ln_b);

    // 2. BatchNorm (writes x_bn into cat slot 0)
    bn_stats_kernel<<<NN_, 256>>>(bn_g, bn_b);
    bn_apply_kernel<<<BNT/4/256, 256>>>();

    // 3. xp = x_ln @ li_w^T + li_b   (M=16384, N=512, K=512, TRANSB)
    {
        dim3 g(TT_/128, (BSZ*NN_)/128, 1);
        gemm_bf3_kernel<true><<<g, 256>>>(xln, li_w, 0, li_b, xp,
            BSZ*NN_, TT_, TT_, TT_, TT_, TT_, 0, 0, 0, 1.f, 0.f, 0);
    }
    // 4. scores = xp @ xp^T (batched 64 x [256x256x512], TRANSB)
    {
        dim3 g(NN_/128, NN_/128, BSZ);
        gemm_bf3_kernel<true><<<g, 256>>>(xp, xp, 0, 0, sc,
            NN_, NN_, TT_, TT_, TT_, NN_,
            (long)NN_*TT_, (long)NN_*TT_, (long)NN_*NN_, 1.f, 0.f, 0);
    }
    // 5. top-k threshold + dis prior + relu + degree
    topk_kernel<<<BSZ*NN_, 256>>>(dis);
    // 6. L = D^-1/2 A D^-1/2 (in place)
    lscale_kernel<<<BNN/4/256, 256>>>();

    // 7. Tx1 = L @ Tx0  -> cat slot 1
    {
        dim3 g(TT_/128, NN_/128, BSZ);
        gemm_bf3_kernel<false><<<g, 256>>>(sc, cat, 0, 0, cat + TT_,
            NN_, TT_, NN_, NN_, KCAT, KCAT,
            (long)NN_*NN_, (long)NN_*KCAT, (long)NN_*KCAT, 1.f, 0.f, 0);
    }
    // 8. Tx2 = 2*L @ Tx1 - Tx0 -> cat slot 2
    {
        dim3 g(TT_/128, NN_/128, BSZ);
        gemm_bf3_kernel<false><<<g, 256>>>(sc, cat + TT_, cat, 0, cat + 2*TT_,
            NN_, TT_, NN_, NN_, KCAT, KCAT,
            (long)NN_*NN_, (long)NN_*KCAT, (long)NN_*KCAT, 2.f, -1.f, 0);
    }
    // 9. out = relu(cat @ cheb_w_flat + cheb_b)  (M=16384, N=512, K=1536)
    {
        dim3 g(TT_/128, (BSZ*NN_)/128, 1);
        gemm_bf3_kernel<false><<<g, 256>>>(cat, cheb_w, 0, cheb_b, out,
            BSZ*NN_, TT_, KCAT, KCAT, TT_, TT_, 0, 0, 0, 1.f, 0.f, 1);
    }
}

// round 8
// speedup vs baseline: 2.2979x; 1.0263x over previous
#include <cuda_runtime.h>
#include <cuda_bf16.h>
#include <cstdint>

// Problem constants
#define BSZ 64
#define NN_ 256
#define TT_ 512
#define NT_ (NN_*TT_)          // 131072
#define BNT (BSZ*NN_*TT_)      // 8388608
#define BNN (BSZ*NN_*NN_)      // 4194304
#define NMAX 51                // 256/5
#define KCAT 1536              // 3*T concatenated Chebyshev inputs
#define CATN ((long)BSZ*NN_*KCAT)

// -------- scratch (device globals; no allocation allowed) --------
__device__ __align__(256) float g_xln[BNT];   // fp32 (bn stats path)
__device__ __align__(256) float g_sc [BNN];   // scores -> A (topk in place)
__device__ __align__(256) float g_tx0[BNT];   // x_bn fp32 (D operand of Tx2)
__device__ __align__(256) __nv_bfloat16 g_xlnh[BNT];
__device__ __align__(256) __nv_bfloat16 g_xlnl[BNT];
__device__ __align__(256) __nv_bfloat16 g_xph [BNT];
__device__ __align__(256) __nv_bfloat16 g_xpl [BNT];
__device__ __align__(256) __nv_bfloat16 g_sch [BNN];
__device__ __align__(256) __nv_bfloat16 g_scl [BNN];
__device__ __align__(256) __nv_bfloat16 g_cath[CATN];
__device__ __align__(256) __nv_bfloat16 g_catl[CATN];
__device__ __align__(256) __nv_bfloat16 g_liwh[TT_*TT_];
__device__ __align__(256) __nv_bfloat16 g_liwl[TT_*TT_];
__device__ __align__(256) __nv_bfloat16 g_chwh[KCAT*TT_];
__device__ __align__(256) __nv_bfloat16 g_chwl[KCAT*TT_];
__device__ float g_mu  [BSZ];
__device__ float g_rstd[BSZ];
__device__ float g_bns [NN_];
__device__ float g_bnh [NN_];
__device__ __align__(256) float g_dinv[BSZ*NN_];

// ======================= helpers =======================
__device__ __forceinline__ uint32_t smem_u32(const void* p) {
    uint32_t a;
    asm("{ .reg .u64 t; cvta.to.shared.u64 t, %1; cvt.u32.u64 %0, t; }"
        : "=r"(a) : "l"(p));
    return a;
}
__device__ __forceinline__ void cpasync16(uint32_t dst, const void* src) {
    asm volatile("cp.async.cg.shared.global [%0], [%1], 16;"
                 :: "r"(dst), "l"(src) : "memory");
}
#define CP_COMMIT() asm volatile("cp.async.commit_group;" ::: "memory")
#define CP_WAIT0()  asm volatile("cp.async.wait_group 0;" ::: "memory")
#define CP_WAIT1()  asm volatile("cp.async.wait_group 1;" ::: "memory")

__device__ __forceinline__ void ldsm_x4(uint32_t addr, uint32_t* r) {
    asm volatile("ldmatrix.sync.aligned.m8n8.x4.shared.b16 {%0,%1,%2,%3}, [%4];"
        : "=r"(r[0]), "=r"(r[1]), "=r"(r[2]), "=r"(r[3]) : "r"(addr));
}
__device__ __forceinline__ void ldsm_x4_t(uint32_t addr, uint32_t* r) {
    asm volatile("ldmatrix.sync.aligned.m8n8.x4.trans.shared.b16 {%0,%1,%2,%3}, [%4];"
        : "=r"(r[0]), "=r"(r[1]), "=r"(r[2]), "=r"(r[3]) : "r"(addr));
}
__device__ __forceinline__ void mma_bf16(float* c, const uint32_t* a,
                                         uint32_t b0, uint32_t b1) {
    asm volatile(
        "mma.sync.aligned.m16n8k16.row.col.f32.bf16.bf16.f32 "
        "{%0,%1,%2,%3}, {%4,%5,%6,%7}, {%8,%9}, {%0,%1,%2,%3};"
        : "+f"(c[0]), "+f"(c[1]), "+f"(c[2]), "+f"(c[3])
        : "r"(a[0]), "r"(a[1]), "r"(a[2]), "r"(a[3]), "r"(b0), "r"(b1));
}
__device__ __forceinline__ unsigned pack_bf2(float a, float b) {
    __nv_bfloat162 h = __floats2bfloat162_rn(a, b);
    return *reinterpret_cast<unsigned*>(&h);
}
__device__ __forceinline__ void split_bf(float v, float& hi, float& lo) {
    __nv_bfloat16 h = __float2bfloat16_rn(v);
    hi = __bfloat162float(h);
    lo = v - hi;
}
__device__ __forceinline__ void split4_store(float4 o, __nv_bfloat16* H,
                                             __nv_bfloat16* L, long idx) {
    float h0,h1,h2,h3,l0,l1,l2,l3;
    split_bf(o.x,h0,l0); split_bf(o.y,h1,l1);
    split_bf(o.z,h2,l2); split_bf(o.w,h3,l3);
    uint2 hh; hh.x = pack_bf2(h0,h1); hh.y = pack_bf2(h2,h3);
    uint2 ll; ll.x = pack_bf2(l0,l1); ll.y = pack_bf2(l2,l3);
    *(uint2*)(H + idx) = hh;
    *(uint2*)(L + idx) = ll;
}

// ======================= GEMM (bf16 3-product, cp.async + ldmatrix) ==========
// C = alpha*A@op(B) + beta*D (+bias) (+relu); optional split bf16 outputs Ch/Cl.
// A (hi/lo bf16): MxK row-major. B: TRANSB ? NxK row-major : KxN row-major.
// CTA tile 128x128, K-chunk 16, 2-stage cp.async pipeline. 40KB smem (no opt-in).
// smem per stage: A 128 rows x 80B ([hi 32B][lo 32B][pad 16B]);
//   TRANSB B: same layout (128 n-rows); NN B: 16 k-rows x 528B ([hi 256B][lo 256B][pad]).
#define ATILE 10240
#define BUFSZ 20480
#define SMEM_GEMM (2*BUFSZ)    // 40960 < 48KB default limit

template<bool TRANSB>
__global__ __launch_bounds__(256, 2)
void gemm_tc_kernel(const __nv_bfloat16* __restrict__ Ahg, const __nv_bfloat16* __restrict__ Alg,
                    const __nv_bfloat16* __restrict__ Bhg, const __nv_bfloat16* __restrict__ Blg,
                    const float* __restrict__ D, const float* __restrict__ bias,
                    float* __restrict__ C,
                    __nv_bfloat16* __restrict__ Ch, __nv_bfloat16* __restrict__ Cl,
                    int Kd, int ldA, int ldB, int ldC, int ldD,
                    long sA, long sB, long sC, long sD,
                    float alpha, float beta, int relu) {
    extern __shared__ __align__(128) char smem[];
    uint32_t sb = smem_u32(smem);

    int tid = threadIdx.x, lane = tid & 31, warp = tid >> 5;
    int z = blockIdx.z;
    Ahg += (long)z * sA; Alg += (long)z * sA;
    Bhg += (long)z * sB; Blg += (long)z * sB;
    if (C)  C  += (long)z * sC;
    if (Ch) { Ch += (long)z * sC; Cl += (long)z * sC; }
    const float* Dp = D ? (D + (long)z * sD) : (const float*)0;
    int rowBase = blockIdx.y * 128;
    int colBase = blockIdx.x * 128;

    int g = lane >> 2, t4 = lane & 3;
    int mW = (warp >> 1) * 32, nW = (warp & 1) * 64;

    // per-lane ldmatrix byte offsets
    uint32_t aoff = (uint32_t)((mW + (lane & 15)) * 80 + ((lane >> 4) << 4));
    uint32_t boff;
    if (TRANSB)
        boff = (uint32_t)((nW + (lane & 7) + ((lane >> 4) << 3)) * 80
                          + (((lane >> 3) & 1) << 4));
    else
        boff = (uint32_t)(((lane & 7) + (((lane >> 3) & 1) << 3)) * 528
                          + (nW + ((lane >> 4) << 3)) * 2);

    float acc[2][8][4];
#pragma unroll
    for (int t = 0; t < 2; t++)
#pragma unroll
        for (int j = 0; j < 8; j++)
#pragma unroll
            for (int c = 0; c < 4; c++) acc[t][j][c] = 0.f;

    int nCh = Kd >> 4;

    auto FILL = [&](int ch, int buf) {
        uint32_t ab = sb + buf * BUFSZ;
        uint32_t bb = ab + ATILE;
        int kt = ch << 4;
        // A: 128 rows x 64B data -> 512 x 16B, 2 per thread
#pragma unroll
        for (int i = 0; i < 2; i++) {
            int idx = tid + (i << 8);
            int r = idx >> 2, c = idx & 3;                   // c: 0,1 hi; 2,3 lo
            const __nv_bfloat16* src = (c < 2 ? Ahg : Alg)
                + (long)(rowBase + r) * ldA + kt + (c & 1) * 8;
            cpasync16(ab + r * 80 + c * 16, src);
        }
        if (TRANSB) {
#pragma unroll
            for (int i = 0; i < 2; i++) {
                int idx = tid + (i << 8);
                int r = idx >> 2, c = idx & 3;
                const __nv_bfloat16* src = (c < 2 ? Bhg : Blg)
                    + (long)(colBase + r) * ldB + kt + (c & 1) * 8;
                cpasync16(bb + r * 80 + c * 16, src);
            }
        } else {
            // B: 16 k-rows x 512B data -> 512 x 16B, 2 per thread
#pragma unroll
            for (int i = 0; i < 2; i++) {
                int idx = tid + (i << 8);
                int k = idx >> 5, c = idx & 31;              // c<16 hi, else lo
                const __nv_bfloat16* src = (c < 16 ? Bhg : Blg)
                    + (long)(kt + k) * ldB + colBase + (c & 15) * 8;
                cpasync16(bb + k * 528 + c * 16, src);
            }
        }
    };

    auto MMASTEP = [&](int buf) {
        uint32_t ab = sb + buf * BUFSZ, bb = ab + ATILE;
        uint32_t ahf[2][4], alf[2][4];
        ldsm_x4(ab + aoff,        ahf[0]);
        ldsm_x4(ab + aoff + 1280, ahf[1]);
        ldsm_x4(ab + aoff + 32,        alf[0]);
        ldsm_x4(ab + aoff + 32 + 1280, alf[1]);
#pragma unroll
        for (int jt = 0; jt < 4; jt++) {
            uint32_t bh[4], bl[4];
            if (TRANSB) {
                ldsm_x4(bb + boff + jt * 1280,      bh);
                ldsm_x4(bb + boff + jt * 1280 + 32, bl);
            } else {
                ldsm_x4_t(bb + boff + jt * 32,       bh);
                ldsm_x4_t(bb + boff + jt * 32 + 256, bl);
            }
#pragma unroll
            for (int j2 = 0; j2 < 2; j2++) {
                int j = jt * 2 + j2;
#pragma unroll
                for (int mt = 0; mt < 2; mt++) {
                    mma_bf16(acc[mt][j], ahf[mt], bh[j2*2], bh[j2*2+1]);
                    mma_bf16(acc[mt][j], alf[mt], bh[j2*2], bh[j2*2+1]);
                    mma_bf16(acc[mt][j], ahf[mt], bl[j2*2], bl[j2*2+1]);
                }
            }
        }
    };

    FILL(0, 0); CP_COMMIT();
    for (int c = 0; c < nCh; c++) {
        if (c + 1 < nCh) { FILL(c + 1, (c + 1) & 1); CP_COMMIT(); CP_WAIT1(); }
        else             { CP_WAIT0(); }
        __syncthreads();
        MMASTEP(c & 1);
        __syncthreads();
    }

    // ---- epilogue ----
#pragma unroll
    for (int mt = 0; mt < 2; mt++) {
#pragma unroll
        for (int j = 0; j < 8; j++) {
            int c0 = colBase + nW + j * 8 + t4 * 2;
            float bs0 = 0.f, bs1 = 0.f;
            if (bias) { bs0 = bias[c0]; bs1 = bias[c0 + 1]; }
#pragma unroll
            for (int rr = 0; rr < 2; rr++) {
                int r = rowBase + mW + mt * 16 + g + rr * 8;
                float v0 = alpha * acc[mt][j][rr * 2 + 0];
                float v1 = alpha * acc[mt][j][rr * 2 + 1];
                if (Dp) {
                    long db = (long)r * ldD + c0;
                    v0 += beta * Dp[db]; v1 += beta * Dp[db + 1];
                }
                v0 += bs0; v1 += bs1;
                if (relu) { v0 = fmaxf(v0, 0.f); v1 = fmaxf(v1, 0.f); }
                long cb = (long)r * ldC + c0;
                if (C) { *(float2*)(C + cb) = make_float2(v0, v1); }
                if (Ch) {
                    float h0,l0,h1,l1;
                    split_bf(v0, h0, l0); split_bf(v1, h1, l1);
                    *(uint32_t*)(Ch + cb) = pack_bf2(h0, h1);
                    *(uint32_t*)(Cl + cb) = pack_bf2(l0, l1);
                }
            }
        }
    }
}

// ======================= elementwise kernels =======================
__global__ void ln_stats_kernel(const float* __restrict__ x) {
    int b = blockIdx.x;
    const float4* xb = (const float4*)(x + (long)b * NT_);
    float s = 0.f, q = 0.f;
    for (int i = threadIdx.x; i < NT_/4; i += 256) {
        float4 v = xb[i];
        s += v.x + v.y + v.z + v.w;
        q += v.x*v.x + v.y*v.y + v.z*v.z + v.w*v.w;
    }
    __shared__ float ss[256], sq[256];
    ss[threadIdx.x] = s; sq[threadIdx.x] = q;
    __syncthreads();
    for (int o = 128; o > 0; o >>= 1) {
        if (threadIdx.x < o) { ss[threadIdx.x] += ss[threadIdx.x+o]; sq[threadIdx.x] += sq[threadIdx.x+o]; }
        __syncthreads();
    }
    if (threadIdx.x == 0) {
        float mu  = ss[0] / (float)NT_;
        float var = sq[0] / (float)NT_ - mu * mu;
        g_mu[b] = mu;
        g_rstd[b] = rsqrtf(var + 1e-5f);
    }
}

__global__ void ln_apply_kernel(const float* __restrict__ x,
                                const float* __restrict__ lw,
                                const float* __restrict__ lb) {
    int i4 = blockIdx.x * 256 + threadIdx.x;
    int base = i4 * 4;
    int b  = base / NT_;
    int nt4 = (base % NT_) / 4;
    float mu = g_mu[b], rs = g_rstd[b];
    float4 v = ((const float4*)x)[i4];
    float4 w = ((const float4*)lw)[nt4];
    float4 bb = ((const float4*)lb)[nt4];
    float4 o;
    o.x = (v.x - mu) * rs * w.x + bb.x;
    o.y = (v.y - mu) * rs * w.y + bb.y;
    o.z = (v.z - mu) * rs * w.z + bb.z;
    o.w = (v.w - mu) * rs * w.w + bb.w;
    ((float4*)g_xln)[i4] = o;
    split4_store(o, g_xlnh, g_xlnl, (long)base);
}

__global__ void bn_stats_kernel(const float* __restrict__ bg,
                                const float* __restrict__ bb) {
    int n = blockIdx.x;
    float s = 0.f, q = 0.f;
    for (int i = threadIdx.x; i < (BSZ*TT_)/4; i += 256) {
        int base = i * 4;
        int b = base / TT_;
        int t = base % TT_;
        float4 v = *(const float4*)&g_xln[((long)b * NN_ + n) * TT_ + t];
        s += v.x + v.y + v.z + v.w;
        q += v.x*v.x + v.y*v.y + v.z*v.z + v.w*v.w;
    }
    __shared__ float ss[256], sq[256];
    ss[threadIdx.x] = s; sq[threadIdx.x] = q;
    __syncthreads();
    for (int o = 128; o > 0; o >>= 1) {
        if (threadIdx.x < o) { ss[threadIdx.x] += ss[threadIdx.x+o]; sq[threadIdx.x] += sq[threadIdx.x+o]; }
        __syncthreads();
    }
    if (threadIdx.x == 0) {
        float cnt  = (float)(BSZ * TT_);
        float mean = ss[0] / cnt;
        float var  = sq[0] / cnt - mean * mean;
        float sc   = bg[n] * rsqrtf(var + 1e-5f);
        g_bns[n] = sc;
        g_bnh[n] = bb[n] - mean * sc;
    }
}

// x_bn -> g_tx0 (fp32, ld TT_) and cat slot 0 (bf16 h/l, ld KCAT)
__global__ void bn_apply_kernel() {
    int i4 = blockIdx.x * 256 + threadIdx.x;
    int base = i4 * 4;
    int row = base / TT_;
    int col = base % TT_;
    int n = row & (NN_ - 1);
    float sc = g_bns[n], sh = g_bnh[n];
    float4 v = ((const float4*)g_xln)[i4];
    float4 o;
    o.x = v.x * sc + sh; o.y = v.y * sc + sh;
    o.z = v.z * sc + sh; o.w = v.w * sc + sh;
    ((float4*)g_tx0)[i4] = o;
    split4_store(o, g_cath, g_catl, (long)row * KCAT + col);
}

__global__ void convert_kernel(const float* __restrict__ src,
                               __nv_bfloat16* __restrict__ h,
                               __nv_bfloat16* __restrict__ l) {
    int i4 = blockIdx.x * 256 + threadIdx.x;
    float4 v = ((const float4*)src)[i4];
    split4_store(v, h, l, (long)i4 * 4);
}

__global__ void topk_kernel(const float* __restrict__ dis) {
    int row = blockIdx.x;
    int n = row & (NN_ - 1);
    int tid = threadIdx.x;
    __shared__ float raw[256], srt[256];
    float v = g_sc[(long)row * NN_ + tid];
    raw[tid] = v; srt[tid] = v;
    __syncthreads();
    for (unsigned k = 2; k <= 256; k <<= 1) {
        for (unsigned j = k >> 1; j > 0; j >>= 1) {
            unsigned ixj = tid ^ j;
            if (ixj > (unsigned)tid) {
                float a = srt[tid], b2 = srt[ixj];
                bool asc = ((tid & k) == 0);
                if ((a > b2) == asc) { srt[tid] = b2; srt[ixj] = a; }
            }
            __syncthreads();
        }
    }
    float kth = srt[256 - NMAX];
    __syncthreads();
    float a = (raw[tid] >= kth) ? raw[tid] : 0.f;
    a += dis[n * NN_ + tid];
    a = fmaxf(a, 0.f);
    srt[tid] = a;
    __syncthreads();
    for (int o = 128; o > 0; o >>= 1) {
        if (tid < o) srt[tid] += srt[tid + o];
        __syncthreads();
    }
    g_sc[(long)row * NN_ + tid] = a;
    if (tid == 0) g_dinv[row] = rsqrtf(srt[0] + 1e-10f);
}

// L = D^-1/2 A D^-1/2 -> bf16 h/l
__global__ void lscale_kernel() {
    int i4 = blockIdx.x * 256 + threadIdx.x;
    int base = i4 * 4;
    int b   = base / (NN_ * NN_);
    int rem = base % (NN_ * NN_);
    int n   = rem / NN_;
    int m   = rem % NN_;
    float dn = g_dinv[b * NN_ + n];
    const float* dm = &g_dinv[b * NN_ + m];
    float4 a = ((const float4*)g_sc)[i4];
    a.x *= dn * dm[0];
    a.y *= dn * dm[1];
    a.z *= dn * dm[2];
    a.w *= dn * dm[3];
    split4_store(a, g_sch, g_scl, (long)base);
}

// ======================= launch =======================
extern "C" void kernel_launch(void* const* d_in, const int* in_sizes, int n_in,
                              void* d_out, int out_size) {
    const float* x      = (const float*)d_in[0];
    const float* dis    = (const float*)d_in[1];
    const float* ln_w   = (const float*)d_in[2];
    const float* ln_b   = (const float*)d_in[3];
    const float* bn_g   = (const float*)d_in[4];
    const float* bn_b   = (const float*)d_in[5];
    const float* li_w   = (const float*)d_in[6];
    const float* li_b   = (const float*)d_in[7];
    const float* cheb_w = (const float*)d_in[8];
    const float* cheb_b = (const float*)d_in[9];
    float* out = (float*)d_out;

    __nv_bfloat16 *xlnh, *xlnl, *xph, *xpl, *sch, *scl, *cath, *catl;
    __nv_bfloat16 *liwh, *liwl, *chwh, *chwl;
    float *sc, *tx0;
    cudaGetSymbolAddress((void**)&xlnh, g_xlnh);
    cudaGetSymbolAddress((void**)&xlnl, g_xlnl);
    cudaGetSymbolAddress((void**)&xph,  g_xph);
    cudaGetSymbolAddress((void**)&xpl,  g_xpl);
    cudaGetSymbolAddress((void**)&sch,  g_sch);
    cudaGetSymbolAddress((void**)&scl,  g_scl);
    cudaGetSymbolAddress((void**)&cath, g_cath);
    cudaGetSymbolAddress((void**)&catl, g_catl);
    cudaGetSymbolAddress((void**)&liwh, g_liwh);
    cudaGetSymbolAddress((void**)&liwl, g_liwl);
    cudaGetSymbolAddress((void**)&chwh, g_chwh);
    cudaGetSymbolAddress((void**)&chwl, g_chwl);
    cudaGetSymbolAddress((void**)&sc,   g_sc);
    cudaGetSymbolAddress((void**)&tx0,  g_tx0);

    // 1. LayerNorm -> xln fp32 + h/l
    ln_stats_kernel<<<BSZ, 256>>>(x);
    ln_apply_kernel<<<BNT/4/256, 256>>>(x, ln_w, ln_b);

    // 2. BatchNorm -> tx0 fp32 + cat slot0 h/l
    bn_stats_kernel<<<NN_, 256>>>(bn_g, bn_b);
    bn_apply_kernel<<<BNT/4/256, 256>>>();

    // 3. weight conversion
    convert_kernel<<<(TT_*TT_)/4/256, 256>>>(li_w, liwh, liwl);
    convert_kernel<<<(KCAT*TT_)/4/256, 256>>>(cheb_w, chwh, chwl);

    // 4. xp = x_ln @ li_w^T + li_b  -> xp h/l
    {
        dim3 g(TT_/128, (BSZ*NN_)/128, 1);
        gemm_tc_kernel<true><<<g, 256, SMEM_GEMM>>>(
            xlnh, xlnl, liwh, liwl, 0, li_b, 0, xph, xpl,
            TT_, TT_, TT_, TT_, 0, 0, 0, 0, 0, 1.f, 0.f, 0);
    }
    // 5. scores = xp @ xp^T  -> sc fp32
    {
        dim3 g(NN_/128, NN_/128, BSZ);
        gemm_tc_kernel<true><<<g, 256, SMEM_GEMM>>>(
            xph, xpl, xph, xpl, 0, 0, sc, 0, 0,
            TT_, TT_, TT_, NN_, 0,
            (long)NT_, (long)NT_, (long)NN_*NN_, 0, 1.f, 0.f, 0);
    }
    // 6. top-k + dis prior + relu + degree
    topk_kernel<<<BSZ*NN_, 256>>>(dis);
    // 7. L -> sc h/l
    lscale_kernel<<<BNN/4/256, 256>>>();

    // 8. Tx1 = L @ Tx0 -> cat slot1 h/l
    {
        dim3 g(TT_/128, NN_/128, BSZ);
        gemm_tc_kernel<false><<<g, 256, SMEM_GEMM>>>(
            sch, scl, cath, catl, 0, 0, 0, cath + TT_, catl + TT_,
            NN_, NN_, KCAT, KCAT, 0,
            (long)NN_*NN_, (long)NN_*KCAT, (long)NN_*KCAT, 0, 1.f, 0.f, 0);
    }
    // 9. Tx2 = 2*L @ Tx1 - Tx0 -> cat slot2 h/l
    {
        dim3 g(TT_/128, NN_/128, BSZ);
        gemm_tc_kernel<false><<<g, 256, SMEM_GEMM>>>(
            sch, scl, cath + TT_, catl + TT_, tx0, 0, 0, cath + 2*TT_, catl + 2*TT_,
            NN_, NN_, KCAT, KCAT, TT_,
            (long)NN_*NN_, (long)NN_*KCAT, (long)NN_*KCAT, (long)NT_,
            2.f, -1.f, 0);
    }
    // 10. out = relu(cat @ cheb_flat + cheb_b)
    {
        dim3 g(TT_/128, (BSZ*NN_)/128, 1);
        gemm_tc_kernel<false><<<g, 256, SMEM_GEMM>>>(
            cath, catl, chwh, chwl, 0, cheb_b, out, 0, 0,
            KCAT, KCAT, TT_, TT_, 0, 0, 0, 0, 0, 1.f, 0.f, 1);
    }
}